// round 3
// baseline (speedup 1.0000x reference)
#include <cuda_runtime.h>
#include <cstdint>

// Problem constants
#define BB 128
#define TT 256
#define DD 768
#define SS 128
#define NROWS (BB*TT)   // 32768

#define PITCHF 24   // floats per smem row: 8 float2 pairs (16f) + 8f pad (bank-conflict-free)

// Scratch (allocation-free rule: __device__ globals)
__device__ float g_Bx[NROWS * SS];      // 16.8 MB
__device__ float g_states[NROWS * SS];  // 16.8 MB

// ---------------------------------------------------------------------------
// tf32 helpers (legacy mma.sync path -- tcgen05 PTX is rejected: harness
// compiles PTX at .target sm_103 without the 'a' feature suffix)
// ---------------------------------------------------------------------------
__device__ __forceinline__ uint32_t f2tf32(float f) {
    uint32_t u;
    asm("cvt.rna.tf32.f32 %0, %1;" : "=r"(u) : "f"(f));
    return u;
}
__device__ __forceinline__ void mma8(float* c, const uint32_t* a, const uint32_t* b) {
    asm volatile(
        "mma.sync.aligned.m16n8k8.row.col.f32.tf32.tf32.f32 "
        "{%0,%1,%2,%3}, {%4,%5,%6,%7}, {%8,%9}, {%0,%1,%2,%3};"
        : "+f"(c[0]), "+f"(c[1]), "+f"(c[2]), "+f"(c[3])
        : "r"(a[0]), "r"(a[1]), "r"(a[2]), "r"(a[3]),
          "r"(b[0]), "r"(b[1]));
}

// ---------------------------------------------------------------------------
// Two-segment tf32 GEMM: C[M,128-tile] = A0[M,K0]*W0[.,K0]^T + A1[M,K1]*W1[.,K1]^T
// Block tile 128x128, BK=16, 256 threads (8 warps 4x2, warp tile 32x64).
// Smem layout: row-major pairs {X[r][k], X[r][k+4]} (k in 8-group), row pitch
// 24 floats -> fragment LDS.64 loads are conflict-free; A frag = 2 LDS.64,
// B frag = 1 LDS.64 (half the LDS issue count of scalar layout).
// 48KB smem/CTA + 128-reg cap -> 2 CTAs/SM.
// ---------------------------------------------------------------------------
__global__ void __launch_bounds__(256, 2)
gemm_tc(const float* __restrict__ A0, int lda0,
        const float* __restrict__ W0, int ldw0, int K0,
        const float* __restrict__ A1, int lda1,
        const float* __restrict__ W1, int ldw1, int K1,
        float* __restrict__ Cp, int ldc)
{
    __shared__ float As[2][128 * PITCHF];
    __shared__ float Bs[2][128 * PITCHF];

    const int tid  = threadIdx.x;
    const int lane = tid & 31;
    const int wid  = tid >> 5;
    const int wm   = wid >> 1;   // 0..3
    const int wn   = wid & 1;    // 0..1
    const int rowBlock = blockIdx.y * 128;
    const int colBlock = blockIdx.x * 128;

    // Producer mapping: thread -> (row 0..127, kf half 0/1); loads 8 floats of
    // A and 8 of B per tile (two float4 = one 8-k group).
    const int prow = tid >> 1;
    const int pkf  = tid & 1;

    const int kt0 = K0 >> 4;
    const int NT  = kt0 + (K1 >> 4);

    float acc[2][8][4];
#pragma unroll
    for (int mi = 0; mi < 2; ++mi)
#pragma unroll
        for (int ni = 0; ni < 8; ++ni)
#pragma unroll
            for (int j = 0; j < 4; ++j) acc[mi][ni][j] = 0.f;

    float4 alo, ahi, blo, bhi;

    auto loadT = [&](int t) {
        const float* Ap; const float* Wp; int la, lw, kb;
        if (t < kt0) { Ap = A0; la = lda0; Wp = W0; lw = ldw0; kb = t << 4; }
        else         { Ap = A1; la = lda1; Wp = W1; lw = ldw1; kb = (t - kt0) << 4; }
        const float* ap = Ap + (size_t)(rowBlock + prow) * la + kb + pkf * 8;
        alo = *(const float4*)ap;
        ahi = *(const float4*)(ap + 4);
        const float* wp = Wp + (size_t)(colBlock + prow) * lw + kb + pkf * 8;
        blo = *(const float4*)wp;
        bhi = *(const float4*)(wp + 4);
    };
    // Pairs: pair j (j=0..3) = {lo[j], hi[j]} -> (k=j, k=j+4) of this 8-group.
    auto stsT = [&](int buf) {
        const int base = prow * PITCHF + pkf * 8;
        uint32_t* a = (uint32_t*)&As[buf][base];
        uint32_t* b = (uint32_t*)&Bs[buf][base];
        // STS.128 #1: pairs 0,1 ; #2: pairs 2,3
        uint4 v;
        v.x = f2tf32(alo.x); v.y = f2tf32(ahi.x); v.z = f2tf32(alo.y); v.w = f2tf32(ahi.y);
        *(uint4*)a = v;
        v.x = f2tf32(alo.z); v.y = f2tf32(ahi.z); v.z = f2tf32(alo.w); v.w = f2tf32(ahi.w);
        *(uint4*)(a + 4) = v;
        v.x = f2tf32(blo.x); v.y = f2tf32(bhi.x); v.z = f2tf32(blo.y); v.w = f2tf32(bhi.y);
        *(uint4*)b = v;
        v.x = f2tf32(blo.z); v.y = f2tf32(bhi.z); v.z = f2tf32(blo.w); v.w = f2tf32(bhi.w);
        *(uint4*)(b + 4) = v;
    };

    loadT(0);
    stsT(0);
    __syncthreads();

    const int klow = lane & 3;
    const int qr   = lane >> 2;

    for (int t = 0; t < NT; ++t) {
        const int cur = t & 1;
        const bool hasNext = (t + 1) < NT;
        if (hasNext) loadT(t + 1);

#pragma unroll
        for (int kf = 0; kf < 2; ++kf) {
            const int po = kf * 8 + klow * 2;  // float offset of this pair
            uint32_t af[2][4];
#pragma unroll
            for (int mi = 0; mi < 2; ++mi) {
                const int r = wm * 32 + mi * 16 + qr;
                float2 qA = *(const float2*)&As[cur][r * PITCHF + po];
                float2 qB = *(const float2*)&As[cur][(r + 8) * PITCHF + po];
                af[mi][0] = __float_as_uint(qA.x);
                af[mi][1] = __float_as_uint(qB.x);
                af[mi][2] = __float_as_uint(qA.y);
                af[mi][3] = __float_as_uint(qB.y);
            }
            uint32_t bf[8][2];
#pragma unroll
            for (int ni = 0; ni < 8; ++ni) {
                const int c = wn * 64 + ni * 8 + qr;
                float2 q = *(const float2*)&Bs[cur][c * PITCHF + po];
                bf[ni][0] = __float_as_uint(q.x);
                bf[ni][1] = __float_as_uint(q.y);
            }
#pragma unroll
            for (int mi = 0; mi < 2; ++mi)
#pragma unroll
                for (int ni = 0; ni < 8; ++ni)
                    mma8(acc[mi][ni], af[mi], bf[ni]);
        }

        if (hasNext) stsT(cur ^ 1);
        __syncthreads();
    }

    // Epilogue: c0,c1 -> (r, c..c+1); c2,c3 -> (r+8, c..c+1)
#pragma unroll
    for (int mi = 0; mi < 2; ++mi) {
#pragma unroll
        for (int ni = 0; ni < 8; ++ni) {
            const int r = rowBlock + wm * 32 + mi * 16 + qr;
            const int c = colBlock + wn * 64 + ni * 8 + 2 * klow;
            *(float2*)&Cp[(size_t)r * ldc + c]       = make_float2(acc[mi][ni][0], acc[mi][ni][1]);
            *(float2*)&Cp[(size_t)(r + 8) * ldc + c] = make_float2(acc[mi][ni][2], acc[mi][ni][3]);
        }
    }
}

// ---------------------------------------------------------------------------
// Sequential scan: one block per batch b. 512 threads = (s in [0,128)) x
// (q in [0,4)) K-quarters. A rows in registers; state broadcast via smem.
// 4 accumulators to cut the dependent-FMA chain to depth 8.
// ---------------------------------------------------------------------------
__global__ void __launch_bounds__(512)
scan_kernel(const float* __restrict__ A)
{
    __shared__ float st[SS];
    __shared__ float part[4][SS];

    const int tid = threadIdx.x;
    const int s = tid & 127;
    const int q = tid >> 7;

    float a[32];
    const float4* arp = (const float4*)(A + s * SS + q * 32);
#pragma unroll
    for (int j = 0; j < 8; ++j) {
        float4 v = arp[j];
        a[4 * j]     = v.x; a[4 * j + 1] = v.y;
        a[4 * j + 2] = v.z; a[4 * j + 3] = v.w;
    }

    if (tid < SS) st[tid] = 0.f;

    const int b = blockIdx.x;
    const float* bx = g_Bx + (size_t)b * TT * SS;
    float* so = g_states + (size_t)b * TT * SS;

    float bxv = (q == 0) ? bx[s] : 0.f;
    __syncthreads();

    for (int t = 0; t < TT; ++t) {
        float p0 = 0.f, p1 = 0.f, p2 = 0.f, p3 = 0.f;
        const float4* stv = (const float4*)(st + q * 32);
#pragma unroll
        for (int j = 0; j < 8; ++j) {
            float4 v = stv[j];
            p0 = fmaf(a[4 * j],     v.x, p0);
            p1 = fmaf(a[4 * j + 1], v.y, p1);
            p2 = fmaf(a[4 * j + 2], v.z, p2);
            p3 = fmaf(a[4 * j + 3], v.w, p3);
        }
        part[q][s] = (p0 + p1) + (p2 + p3);
        __syncthreads();
        if (q == 0) {
            float v = part[0][s] + part[1][s] + part[2][s] + part[3][s] + bxv;
            v = fminf(fmaxf(v, -10.f), 10.f);
            st[s] = v;
            so[t * SS + s] = v;
            if (t + 1 < TT) bxv = bx[(t + 1) * SS + s];
        }
        __syncthreads();
    }
}

// ---------------------------------------------------------------------------
// Fused gate + residual mix + LayerNorm. One block (128 threads) per row.
// Near the HBM roofline (300MB traffic); unchanged.
// ---------------------------------------------------------------------------
__global__ void __launch_bounds__(128)
mix_ln_kernel(const float* __restrict__ x,
              const float* __restrict__ gate_w,
              const float* __restrict__ gate_b,
              const float* __restrict__ gamma,
              const float* __restrict__ beta,
              float* __restrict__ io)
{
    __shared__ float red[4][2];

    const int row = blockIdx.x;
    const int tid = threadIdx.x;
    const int lane = tid & 31, w = tid >> 5;
    const float* xr = x + (size_t)row * DD;
    float* tr = io + (size_t)row * DD;

    float xs[6], ts[6];
    float l0 = 0.f, l1 = 0.f;
#pragma unroll
    for (int k = 0; k < 6; ++k) {
        const int i = tid + k * 128;
        xs[k] = xr[i];
        ts[k] = tr[i];
        l0 = fmaf(xs[k], gate_w[i], l0);
        l1 = fmaf(xs[k], gate_w[DD + i], l1);
    }
#pragma unroll
    for (int o = 16; o; o >>= 1) {
        l0 += __shfl_xor_sync(0xffffffffu, l0, o);
        l1 += __shfl_xor_sync(0xffffffffu, l1, o);
    }
    if (lane == 0) { red[w][0] = l0; red[w][1] = l1; }
    __syncthreads();
    l0 = red[0][0] + red[1][0] + red[2][0] + red[3][0] + gate_b[0];
    l1 = red[0][1] + red[1][1] + red[2][1] + red[3][1] + gate_b[1];

    const float mx = fmaxf(l0, l1);
    const float e0 = expf(l0 - mx), e1 = expf(l1 - mx);
    const float inv = 1.f / (e0 + e1);
    const float g0 = e0 * inv, g1 = e1 * inv;

    float mix[6];
    float s = 0.f, s2 = 0.f;
#pragma unroll
    for (int k = 0; k < 6; ++k) {
        mix[k] = g0 * ts[k] + g1 * xs[k];
        s += mix[k];
        s2 = fmaf(mix[k], mix[k], s2);
    }
    __syncthreads();
#pragma unroll
    for (int o = 16; o; o >>= 1) {
        s  += __shfl_xor_sync(0xffffffffu, s, o);
        s2 += __shfl_xor_sync(0xffffffffu, s2, o);
    }
    if (lane == 0) { red[w][0] = s; red[w][1] = s2; }
    __syncthreads();
    s  = red[0][0] + red[1][0] + red[2][0] + red[3][0];
    s2 = red[0][1] + red[1][1] + red[2][1] + red[3][1];

    const float mu = s * (1.f / DD);
    float var = s2 * (1.f / DD) - mu * mu;
    var = fmaxf(var, 0.f);
    const float rstd = rsqrtf(var + 1e-5f);

#pragma unroll
    for (int k = 0; k < 6; ++k) {
        const int i = tid + k * 128;
        tr[i] = (mix[k] - mu) * rstd * gamma[i] + beta[i];
    }
}

// ---------------------------------------------------------------------------
// Launch
// ---------------------------------------------------------------------------
extern "C" void kernel_launch(void* const* d_in, const int* in_sizes, int n_in,
                              void* d_out, int out_size)
{
    const float* x      = (const float*)d_in[0];
    const float* A      = (const float*)d_in[1];
    const float* B_w    = (const float*)d_in[2];
    const float* C_w    = (const float*)d_in[3];
    const float* D_w    = (const float*)d_in[4];
    const float* gate_w = (const float*)d_in[5];
    const float* gate_b = (const float*)d_in[6];
    const float* gamma  = (const float*)d_in[7];
    const float* beta   = (const float*)d_in[8];
    float* out = (float*)d_out;

    float *Bx = nullptr, *St = nullptr;
    cudaGetSymbolAddress((void**)&Bx, g_Bx);
    cudaGetSymbolAddress((void**)&St, g_states);

    // 1) Bx = x @ B_w^T   [32768 x 128], K = 768 (single segment)
    gemm_tc<<<dim3(1, NROWS / 128), 256>>>(
        x, DD, B_w, DD, DD,
        x, DD, B_w, DD, 0,
        Bx, SS);

    // 2) sequential scan -> states
    scan_kernel<<<BB, 512>>>(A);

    // 3) out = states @ C_w^T + x @ D_w^T   [32768 x 768], K = 128 + 768
    gemm_tc<<<dim3(DD / 128, NROWS / 128), 256>>>(
        St, SS, C_w, SS, SS,
        x, DD, D_w, DD, DD,
        out, DD);

    // 4) gate + residual mix + LayerNorm (in place on d_out)
    mix_ln_kernel<<<NROWS, 128>>>(x, gate_w, gate_b, gamma, beta, out);
}

// round 4
// speedup vs baseline: 1.4950x; 1.4950x over previous
#include <cuda_runtime.h>
#include <cuda_fp16.h>
#include <cstdint>

// Problem constants
#define BB 128
#define TT 256
#define DD 768
#define SS 128
#define NROWS (BB*TT)   // 32768

#define PITCHW 24   // smem row pitch in 32-bit words (96B): conflict-free fragment LDS.64

// Scratch (allocation-free rule: __device__ globals)
__device__ float  g_Bx[NROWS * SS];        // 16.8 MB (f32: feeds scan)
__device__ __half g_states_h[NROWS * SS];  // 8.4 MB
__device__ __half g_xh[NROWS * DD];        // 50.3 MB
__device__ __half g_Bw_h[SS * DD];
__device__ __half g_Cw_h[DD * SS];
__device__ __half g_Dw_h[DD * DD];

// ---------------------------------------------------------------------------
// helpers
// ---------------------------------------------------------------------------
__device__ __forceinline__ uint32_t packh2(float lo, float hi) {
    __half2 h = __floats2half2_rn(lo, hi);
    return *(uint32_t*)&h;
}
__device__ __forceinline__ void mma16(float* c, const uint32_t* a, const uint32_t* b) {
    asm volatile(
        "mma.sync.aligned.m16n8k16.row.col.f32.f16.f16.f32 "
        "{%0,%1,%2,%3}, {%4,%5,%6,%7}, {%8,%9}, {%0,%1,%2,%3};"
        : "+f"(c[0]), "+f"(c[1]), "+f"(c[2]), "+f"(c[3])
        : "r"(a[0]), "r"(a[1]), "r"(a[2]), "r"(a[3]),
          "r"(b[0]), "r"(b[1]));
}

// Smem tile layout (per 128-row matrix, BK=32):
//   row r, k-half h (16 k each), group g in 0..3:
//   words [r*24 + h*8 + 2g .. +1] = fp16x2 {k=2g,2g+1} and {k=2g+8,2g+9}  (k rel. to 16h)
// Fragment for mma.m16n8k16 at (row r, h): LDS.64 -> {a0,a2}; row r+8 -> {a1,a3};
// B at (col n, h): LDS.64 -> {b0,b1}.

// ---------------------------------------------------------------------------
// GEMM1: Bx[M,128] = x[M,768](f32) @ B_w_h[128,768]^T ; also emits x_h (fp16 copy of x)
// Block tile 128x128 (grid.x=1), BK=32, 256 threads, 8 warps (4x2), warp tile 32x64.
// ---------------------------------------------------------------------------
__global__ void __launch_bounds__(256, 2)
gemm1_kernel(const float* __restrict__ x,
             const __half* __restrict__ Wh,
             float* __restrict__ Cp,
             __half* __restrict__ xh)
{
    __shared__ uint32_t As[2][128 * PITCHW];
    __shared__ uint32_t Bs[2][128 * PITCHW];

    const int tid  = threadIdx.x;
    const int lane = tid & 31;
    const int wid  = tid >> 5;
    const int wm   = wid >> 1;
    const int wn   = wid & 1;
    const int rowBlock = blockIdx.y * 128;

    const int prow = tid >> 1;
    const int ph   = tid & 1;

    const int NT = DD / 32;  // 24

    float acc[2][8][4];
#pragma unroll
    for (int mi = 0; mi < 2; ++mi)
#pragma unroll
        for (int ni = 0; ni < 8; ++ni)
#pragma unroll
            for (int j = 0; j < 4; ++j) acc[mi][ni][j] = 0.f;

    uint32_t va[8], vb[8];

    auto loadT = [&](int t) {
        const int kb = t * 32;
        // A: 16 f32 -> 8 fp16x2 words; also STG fp16 copy
        const float4* ap = (const float4*)(x + (size_t)(rowBlock + prow) * DD + kb + ph * 16);
#pragma unroll
        for (int i = 0; i < 4; ++i) {
            float4 f = ap[i];
            va[2 * i]     = packh2(f.x, f.y);
            va[2 * i + 1] = packh2(f.z, f.w);
        }
        uint4* xo = (uint4*)(xh + (size_t)(rowBlock + prow) * DD + kb + ph * 16);
        xo[0] = make_uint4(va[0], va[1], va[2], va[3]);
        xo[1] = make_uint4(va[4], va[5], va[6], va[7]);
        // W: 16 fp16
        const uint4* wp = (const uint4*)(Wh + (size_t)prow * DD + kb + ph * 16);
        uint4 w0 = wp[0], w1 = wp[1];
        vb[0] = w0.x; vb[1] = w0.y; vb[2] = w0.z; vb[3] = w0.w;
        vb[4] = w1.x; vb[5] = w1.y; vb[6] = w1.z; vb[7] = w1.w;
    };
    auto stsT = [&](int buf) {
        const int base = prow * PITCHW + ph * 8;
        *(uint4*)&As[buf][base]     = make_uint4(va[0], va[4], va[1], va[5]);
        *(uint4*)&As[buf][base + 4] = make_uint4(va[2], va[6], va[3], va[7]);
        *(uint4*)&Bs[buf][base]     = make_uint4(vb[0], vb[4], vb[1], vb[5]);
        *(uint4*)&Bs[buf][base + 4] = make_uint4(vb[2], vb[6], vb[3], vb[7]);
    };

    loadT(0);
    stsT(0);
    __syncthreads();

    const int g  = lane & 3;
    const int qr = lane >> 2;

    for (int t = 0; t < NT; ++t) {
        const int cur = t & 1;
        const bool hasNext = (t + 1) < NT;
        if (hasNext) loadT(t + 1);

#pragma unroll
        for (int h = 0; h < 2; ++h) {
            uint32_t af[2][4];
#pragma unroll
            for (int mi = 0; mi < 2; ++mi) {
                const int r = wm * 32 + mi * 16 + qr;
                uint2 lo = *(const uint2*)&As[cur][r * PITCHW + h * 8 + g * 2];
                uint2 hi = *(const uint2*)&As[cur][(r + 8) * PITCHW + h * 8 + g * 2];
                af[mi][0] = lo.x; af[mi][1] = hi.x; af[mi][2] = lo.y; af[mi][3] = hi.y;
            }
            uint32_t bfr[8][2];
#pragma unroll
            for (int ni = 0; ni < 8; ++ni) {
                const int c = wn * 64 + ni * 8 + qr;
                uint2 q = *(const uint2*)&Bs[cur][c * PITCHW + h * 8 + g * 2];
                bfr[ni][0] = q.x; bfr[ni][1] = q.y;
            }
#pragma unroll
            for (int mi = 0; mi < 2; ++mi)
#pragma unroll
                for (int ni = 0; ni < 8; ++ni)
                    mma16(acc[mi][ni], af[mi], bfr[ni]);
        }

        if (hasNext) stsT(cur ^ 1);
        __syncthreads();
    }

#pragma unroll
    for (int mi = 0; mi < 2; ++mi)
#pragma unroll
        for (int ni = 0; ni < 8; ++ni) {
            const int r = rowBlock + wm * 32 + mi * 16 + qr;
            const int c = wn * 64 + ni * 8 + 2 * g;
            *(float2*)&Cp[(size_t)r * SS + c]       = make_float2(acc[mi][ni][0], acc[mi][ni][1]);
            *(float2*)&Cp[(size_t)(r + 8) * SS + c] = make_float2(acc[mi][ni][2], acc[mi][ni][3]);
        }
}

// ---------------------------------------------------------------------------
// GEMM2 (all fp16 inputs, two K segments):
//   C[M,128-tile] = A0[M,K0] @ W0[.,K0]^T + A1[M,K1] @ W1[.,K1]^T   (f32 out)
// ---------------------------------------------------------------------------
__global__ void __launch_bounds__(256, 2)
gemm2_kernel(const __half* __restrict__ A0, const __half* __restrict__ W0, int K0,
             const __half* __restrict__ A1, const __half* __restrict__ W1, int K1,
             float* __restrict__ Cp, int ldc)
{
    __shared__ uint32_t As[2][128 * PITCHW];
    __shared__ uint32_t Bs[2][128 * PITCHW];

    const int tid  = threadIdx.x;
    const int lane = tid & 31;
    const int wid  = tid >> 5;
    const int wm   = wid >> 1;
    const int wn   = wid & 1;
    const int rowBlock = blockIdx.y * 128;
    const int colBlock = blockIdx.x * 128;

    const int prow = tid >> 1;
    const int ph   = tid & 1;

    const int NC0 = K0 >> 5;
    const int NT  = NC0 + (K1 >> 5);

    float acc[2][8][4];
#pragma unroll
    for (int mi = 0; mi < 2; ++mi)
#pragma unroll
        for (int ni = 0; ni < 8; ++ni)
#pragma unroll
            for (int j = 0; j < 4; ++j) acc[mi][ni][j] = 0.f;

    uint32_t va[8], vb[8];

    auto loadT = [&](int t) {
        const __half* Ap; const __half* Wp; int K, kb;
        if (t < NC0) { Ap = A0; Wp = W0; K = K0; kb = t << 5; }
        else         { Ap = A1; Wp = W1; K = K1; kb = (t - NC0) << 5; }
        const uint4* ap = (const uint4*)(Ap + (size_t)(rowBlock + prow) * K + kb + ph * 16);
        uint4 a0 = ap[0], a1 = ap[1];
        va[0] = a0.x; va[1] = a0.y; va[2] = a0.z; va[3] = a0.w;
        va[4] = a1.x; va[5] = a1.y; va[6] = a1.z; va[7] = a1.w;
        const uint4* wp = (const uint4*)(Wp + (size_t)(colBlock + prow) * K + kb + ph * 16);
        uint4 w0 = wp[0], w1 = wp[1];
        vb[0] = w0.x; vb[1] = w0.y; vb[2] = w0.z; vb[3] = w0.w;
        vb[4] = w1.x; vb[5] = w1.y; vb[6] = w1.z; vb[7] = w1.w;
    };
    auto stsT = [&](int buf) {
        const int base = prow * PITCHW + ph * 8;
        *(uint4*)&As[buf][base]     = make_uint4(va[0], va[4], va[1], va[5]);
        *(uint4*)&As[buf][base + 4] = make_uint4(va[2], va[6], va[3], va[7]);
        *(uint4*)&Bs[buf][base]     = make_uint4(vb[0], vb[4], vb[1], vb[5]);
        *(uint4*)&Bs[buf][base + 4] = make_uint4(vb[2], vb[6], vb[3], vb[7]);
    };

    loadT(0);
    stsT(0);
    __syncthreads();

    const int g  = lane & 3;
    const int qr = lane >> 2;

    for (int t = 0; t < NT; ++t) {
        const int cur = t & 1;
        const bool hasNext = (t + 1) < NT;
        if (hasNext) loadT(t + 1);

#pragma unroll
        for (int h = 0; h < 2; ++h) {
            uint32_t af[2][4];
#pragma unroll
            for (int mi = 0; mi < 2; ++mi) {
                const int r = wm * 32 + mi * 16 + qr;
                uint2 lo = *(const uint2*)&As[cur][r * PITCHW + h * 8 + g * 2];
                uint2 hi = *(const uint2*)&As[cur][(r + 8) * PITCHW + h * 8 + g * 2];
                af[mi][0] = lo.x; af[mi][1] = hi.x; af[mi][2] = lo.y; af[mi][3] = hi.y;
            }
            uint32_t bfr[8][2];
#pragma unroll
            for (int ni = 0; ni < 8; ++ni) {
                const int c = wn * 64 + ni * 8 + qr;
                uint2 q = *(const uint2*)&Bs[cur][c * PITCHW + h * 8 + g * 2];
                bfr[ni][0] = q.x; bfr[ni][1] = q.y;
            }
#pragma unroll
            for (int mi = 0; mi < 2; ++mi)
#pragma unroll
                for (int ni = 0; ni < 8; ++ni)
                    mma16(acc[mi][ni], af[mi], bfr[ni]);
        }

        if (hasNext) stsT(cur ^ 1);
        __syncthreads();
    }

#pragma unroll
    for (int mi = 0; mi < 2; ++mi)
#pragma unroll
        for (int ni = 0; ni < 8; ++ni) {
            const int r = rowBlock + wm * 32 + mi * 16 + qr;
            const int c = colBlock + wn * 64 + ni * 8 + 2 * g;
            *(float2*)&Cp[(size_t)r * ldc + c]       = make_float2(acc[mi][ni][0], acc[mi][ni][1]);
            *(float2*)&Cp[(size_t)(r + 8) * ldc + c] = make_float2(acc[mi][ni][2], acc[mi][ni][3]);
        }
}

// ---------------------------------------------------------------------------
// Weight conversion f32 -> fp16 (runs once per launch; tiny)
// ---------------------------------------------------------------------------
__global__ void __launch_bounds__(256)
convert_w_kernel(const float* __restrict__ Bw,
                 const float* __restrict__ Cw,
                 const float* __restrict__ Dw)
{
    const int i = blockIdx.x * blockDim.x + threadIdx.x;
    if (i < SS * DD) g_Bw_h[i] = __float2half(Bw[i]);
    if (i < DD * SS) g_Cw_h[i] = __float2half(Cw[i]);
    if (i < DD * DD) g_Dw_h[i] = __float2half(Dw[i]);
}

// ---------------------------------------------------------------------------
// Sequential scan: one block per batch. 512 thr = (s in [0,128)) x (q quarters).
// States written as fp16 for GEMM2.
// ---------------------------------------------------------------------------
__global__ void __launch_bounds__(512)
scan_kernel(const float* __restrict__ A)
{
    __shared__ float st[SS];
    __shared__ float part[4][SS];

    const int tid = threadIdx.x;
    const int s = tid & 127;
    const int q = tid >> 7;

    float a[32];
    const float4* arp = (const float4*)(A + s * SS + q * 32);
#pragma unroll
    for (int j = 0; j < 8; ++j) {
        float4 v = arp[j];
        a[4 * j]     = v.x; a[4 * j + 1] = v.y;
        a[4 * j + 2] = v.z; a[4 * j + 3] = v.w;
    }

    if (tid < SS) st[tid] = 0.f;

    const int b = blockIdx.x;
    const float* bx = g_Bx + (size_t)b * TT * SS;
    __half* so = g_states_h + (size_t)b * TT * SS;

    float bxv = (q == 0) ? bx[s] : 0.f;
    __syncthreads();

    for (int t = 0; t < TT; ++t) {
        float p0 = 0.f, p1 = 0.f, p2 = 0.f, p3 = 0.f;
        const float4* stv = (const float4*)(st + q * 32);
#pragma unroll
        for (int j = 0; j < 8; ++j) {
            float4 v = stv[j];
            p0 = fmaf(a[4 * j],     v.x, p0);
            p1 = fmaf(a[4 * j + 1], v.y, p1);
            p2 = fmaf(a[4 * j + 2], v.z, p2);
            p3 = fmaf(a[4 * j + 3], v.w, p3);
        }
        part[q][s] = (p0 + p1) + (p2 + p3);
        __syncthreads();
        if (q == 0) {
            float v = part[0][s] + part[1][s] + part[2][s] + part[3][s] + bxv;
            v = fminf(fmaxf(v, -10.f), 10.f);
            st[s] = v;
            so[t * SS + s] = __float2half(v);
            if (t + 1 < TT) bxv = bx[(t + 1) * SS + s];
        }
        __syncthreads();
    }
}

// ---------------------------------------------------------------------------
// Fused gate + residual mix + LayerNorm. One block (128 threads) per row.
// ---------------------------------------------------------------------------
__global__ void __launch_bounds__(128)
mix_ln_kernel(const float* __restrict__ x,
              const float* __restrict__ gate_w,
              const float* __restrict__ gate_b,
              const float* __restrict__ gamma,
              const float* __restrict__ beta,
              float* __restrict__ io)
{
    __shared__ float red[4][2];

    const int row = blockIdx.x;
    const int tid = threadIdx.x;
    const int lane = tid & 31, w = tid >> 5;
    const float* xr = x + (size_t)row * DD;
    float* tr = io + (size_t)row * DD;

    float xs[6], ts[6];
    float l0 = 0.f, l1 = 0.f;
#pragma unroll
    for (int k = 0; k < 6; ++k) {
        const int i = tid + k * 128;
        xs[k] = xr[i];
        ts[k] = tr[i];
        l0 = fmaf(xs[k], gate_w[i], l0);
        l1 = fmaf(xs[k], gate_w[DD + i], l1);
    }
#pragma unroll
    for (int o = 16; o; o >>= 1) {
        l0 += __shfl_xor_sync(0xffffffffu, l0, o);
        l1 += __shfl_xor_sync(0xffffffffu, l1, o);
    }
    if (lane == 0) { red[w][0] = l0; red[w][1] = l1; }
    __syncthreads();
    l0 = red[0][0] + red[1][0] + red[2][0] + red[3][0] + gate_b[0];
    l1 = red[0][1] + red[1][1] + red[2][1] + red[3][1] + gate_b[1];

    const float mx = fmaxf(l0, l1);
    const float e0 = expf(l0 - mx), e1 = expf(l1 - mx);
    const float inv = 1.f / (e0 + e1);
    const float g0 = e0 * inv, g1 = e1 * inv;

    float mix[6];
    float s = 0.f, s2 = 0.f;
#pragma unroll
    for (int k = 0; k < 6; ++k) {
        mix[k] = g0 * ts[k] + g1 * xs[k];
        s += mix[k];
        s2 = fmaf(mix[k], mix[k], s2);
    }
    __syncthreads();
#pragma unroll
    for (int o = 16; o; o >>= 1) {
        s  += __shfl_xor_sync(0xffffffffu, s, o);
        s2 += __shfl_xor_sync(0xffffffffu, s2, o);
    }
    if (lane == 0) { red[w][0] = s; red[w][1] = s2; }
    __syncthreads();
    s  = red[0][0] + red[1][0] + red[2][0] + red[3][0];
    s2 = red[0][1] + red[1][1] + red[2][1] + red[3][1];

    const float mu = s * (1.f / DD);
    float var = s2 * (1.f / DD) - mu * mu;
    var = fmaxf(var, 0.f);
    const float rstd = rsqrtf(var + 1e-5f);

#pragma unroll
    for (int k = 0; k < 6; ++k) {
        const int i = tid + k * 128;
        tr[i] = (mix[k] - mu) * rstd * gamma[i] + beta[i];
    }
}

// ---------------------------------------------------------------------------
// Launch
// ---------------------------------------------------------------------------
extern "C" void kernel_launch(void* const* d_in, const int* in_sizes, int n_in,
                              void* d_out, int out_size)
{
    const float* x      = (const float*)d_in[0];
    const float* A      = (const float*)d_in[1];
    const float* B_w    = (const float*)d_in[2];
    const float* C_w    = (const float*)d_in[3];
    const float* D_w    = (const float*)d_in[4];
    const float* gate_w = (const float*)d_in[5];
    const float* gate_b = (const float*)d_in[6];
    const float* gamma  = (const float*)d_in[7];
    const float* beta   = (const float*)d_in[8];
    float* out = (float*)d_out;

    float  *Bx = nullptr;
    __half *Sh = nullptr, *Xh = nullptr, *BwH = nullptr, *CwH = nullptr, *DwH = nullptr;
    cudaGetSymbolAddress((void**)&Bx,  g_Bx);
    cudaGetSymbolAddress((void**)&Sh,  g_states_h);
    cudaGetSymbolAddress((void**)&Xh,  g_xh);
    cudaGetSymbolAddress((void**)&BwH, g_Bw_h);
    cudaGetSymbolAddress((void**)&CwH, g_Cw_h);
    cudaGetSymbolAddress((void**)&DwH, g_Dw_h);

    // 0) weights f32 -> fp16
    convert_w_kernel<<<(DD * DD + 255) / 256, 256>>>(B_w, C_w, D_w);

    // 1) Bx = x @ B_w^T (also emits x_h)
    gemm1_kernel<<<dim3(1, NROWS / 128), 256>>>(x, BwH, Bx, Xh);

    // 2) sequential scan -> states (fp16)
    scan_kernel<<<BB, 512>>>(A);

    // 3) out = states_h @ C_w^T + x_h @ D_w^T
    gemm2_kernel<<<dim3(DD / 128, NROWS / 128), 256>>>(
        Sh, CwH, SS, Xh, DwH, DD, out, DD);

    // 4) gate + residual mix + LayerNorm (in place on d_out)
    mix_ln_kernel<<<NROWS, 128>>>(x, gate_w, gate_b, gamma, beta, out);
}

// round 5
// speedup vs baseline: 1.9016x; 1.2719x over previous
#include <cuda_runtime.h>
#include <cuda_fp16.h>
#include <cstdint>

// Problem constants
#define BB 128
#define TT 256
#define DD 768
#define SS 128
#define NROWS (BB*TT)   // 32768

// Scratch (allocation-free rule: __device__ globals)
__device__ float  g_Bx[NROWS * SS];        // f32: feeds scan
__device__ __half g_states_h[NROWS * SS];
__device__ __half g_xh[NROWS * DD];
__device__ __half g_Bw_h[SS * DD];
__device__ __half g_Cw_h[DD * SS];
__device__ __half g_Dw_h[DD * DD];

// ---------------------------------------------------------------------------
// helpers
// ---------------------------------------------------------------------------
__device__ __forceinline__ uint32_t packh2(float lo, float hi) {
    __half2 h = __floats2half2_rn(lo, hi);
    return *(uint32_t*)&h;
}
__device__ __forceinline__ void mma16(float* c, const uint32_t* a, const uint32_t* b) {
    asm volatile(
        "mma.sync.aligned.m16n8k16.row.col.f32.f16.f16.f32 "
        "{%0,%1,%2,%3}, {%4,%5,%6,%7}, {%8,%9}, {%0,%1,%2,%3};"
        : "+f"(c[0]), "+f"(c[1]), "+f"(c[2]), "+f"(c[3])
        : "r"(a[0]), "r"(a[1]), "r"(a[2]), "r"(a[3]),
          "r"(b[0]), "r"(b[1]));
}

// Swizzled smem layout for a [rows x 32] fp16 tile:
//   logical (r, k) -> phys row p = r>>1 (128B), chunk q = ((r&1)*4 + k/8) ^ (p&7)
// cp.async writes (16B chunks) and ldmatrix reads (8 rows x 16B) are both
// bank-conflict-free under this mapping.
__device__ __forceinline__ uint32_t sw_off(int r, int k) {
    int p = r >> 1;
    int q = (((r & 1) << 2) | (k >> 3)) ^ (p & 7);
    return (uint32_t)((p << 7) + (q << 4) + ((k & 7) << 1));
}

// ---------------------------------------------------------------------------
// fp16 GEMM, two K segments, cp.async 3-stage pipeline + ldmatrix fragments.
//   C[M, 128-col-tile] = A0[M,K0] @ W0[.,K0]^T + A1[M,K1] @ W1[.,K1]^T  (f32 out)
// BM in {64,128}: CTA tile BM x 128, BM*2 threads, warp tile 32x64, BK=32.
// ---------------------------------------------------------------------------
template<int BM>
__global__ void __launch_bounds__(BM * 2, 256 / BM)
gemm_ca(const __half* __restrict__ A0, const __half* __restrict__ W0, int K0,
        const __half* __restrict__ A1, const __half* __restrict__ W1, int K1,
        float* __restrict__ Cp, int ldc)
{
    constexpr int THREADS = BM * 2;
    constexpr int ABYTES  = BM * 64;      // BM rows x 32 fp16
    constexpr int BBYTES  = 128 * 64;
    constexpr int STAGE   = ABYTES + BBYTES;
    __shared__ __align__(1024) char smem[3 * STAGE];

    const int tid  = threadIdx.x;
    const int lane = tid & 31;
    const int wid  = tid >> 5;
    const int wm   = wid >> 1;                 // 0..BM/32-1
    const int wn   = wid & 1;                  // 0..1
    const int rowBlock = blockIdx.y * BM;
    const int colBlock = blockIdx.x * 128;

    const int NC0 = K0 >> 5;
    const int NT  = NC0 + (K1 >> 5);

    const uint32_t sbase = (uint32_t)__cvta_generic_to_shared(smem);

    float acc[2][8][4];
#pragma unroll
    for (int mi = 0; mi < 2; ++mi)
#pragma unroll
        for (int ni = 0; ni < 8; ++ni)
#pragma unroll
            for (int j = 0; j < 4; ++j) acc[mi][ni][j] = 0.f;

    auto issue_loads = [&](int t) {
        const __half *Ap, *Wp; int K, kb;
        if (t < NC0) { Ap = A0; Wp = W0; K = K0; kb = t << 5; }
        else         { Ap = A1; Wp = W1; K = K1; kb = (t - NC0) << 5; }
        const uint32_t st = sbase + (t % 3) * STAGE;
#pragma unroll
        for (int ch = tid; ch < BM * 4; ch += THREADS) {
            const int r = ch >> 2, c = ch & 3;
            const __half* src = Ap + (size_t)(rowBlock + r) * K + kb + c * 8;
            const uint32_t dst = st + sw_off(r, c * 8);
            asm volatile("cp.async.cg.shared.global [%0], [%1], 16;"
                         :: "r"(dst), "l"(src));
        }
#pragma unroll
        for (int ch = tid; ch < 512; ch += THREADS) {
            const int r = ch >> 2, c = ch & 3;
            const __half* src = Wp + (size_t)(colBlock + r) * K + kb + c * 8;
            const uint32_t dst = st + ABYTES + sw_off(r, c * 8);
            asm volatile("cp.async.cg.shared.global [%0], [%1], 16;"
                         :: "r"(dst), "l"(src));
        }
        asm volatile("cp.async.commit_group;" ::: "memory");
    };

    issue_loads(0);
    issue_loads(1);

    for (int t = 0; t < NT; ++t) {
        asm volatile("cp.async.wait_group 1;" ::: "memory");
        __syncthreads();
        const uint32_t Abase = sbase + (t % 3) * STAGE;
        const uint32_t Bbase = Abase + ABYTES;

#pragma unroll
        for (int kf = 0; kf < 2; ++kf) {
            // A fragments: 16x16 per mi via ldmatrix.x4 (regs land as a0..a3)
            uint32_t af[2][4];
#pragma unroll
            for (int mi = 0; mi < 2; ++mi) {
                const int row = wm * 32 + mi * 16 + (lane & 7) + ((lane >> 3) & 1) * 8;
                const int kb  = kf * 16 + ((lane >> 4) & 1) * 8;
                const uint32_t addr = Abase + sw_off(row, kb);
                asm volatile("ldmatrix.sync.aligned.m8n8.x4.shared.b16 {%0,%1,%2,%3}, [%4];"
                             : "=r"(af[mi][0]), "=r"(af[mi][1]),
                               "=r"(af[mi][2]), "=r"(af[mi][3]) : "r"(addr));
            }
            // B fragments: two ni per ldmatrix.x4 -> {b0,b1,b0',b1'}
            uint32_t bf[8][2];
#pragma unroll
            for (int nj = 0; nj < 4; ++nj) {
                const int n  = wn * 64 + nj * 16 + (lane & 7) + ((lane >> 4) & 1) * 8;
                const int kb = kf * 16 + ((lane >> 3) & 1) * 8;
                const uint32_t addr = Bbase + sw_off(n, kb);
                uint32_t q0, q1, q2, q3;
                asm volatile("ldmatrix.sync.aligned.m8n8.x4.shared.b16 {%0,%1,%2,%3}, [%4];"
                             : "=r"(q0), "=r"(q1), "=r"(q2), "=r"(q3) : "r"(addr));
                bf[nj * 2][0] = q0;     bf[nj * 2][1] = q1;
                bf[nj * 2 + 1][0] = q2; bf[nj * 2 + 1][1] = q3;
            }
            // Overlap: issue next-next tile's async loads between LDSM and MMA
            if (kf == 0 && t + 2 < NT) issue_loads(t + 2);
#pragma unroll
            for (int mi = 0; mi < 2; ++mi)
#pragma unroll
                for (int ni = 0; ni < 8; ++ni)
                    mma16(acc[mi][ni], af[mi], bf[ni]);
        }
        __syncthreads();
    }

    // Epilogue: lane -> (row qr, col pair 2*g); f32 float2 stores
    const int g  = lane & 3;
    const int qr = lane >> 2;
#pragma unroll
    for (int mi = 0; mi < 2; ++mi)
#pragma unroll
        for (int ni = 0; ni < 8; ++ni) {
            const int r = rowBlock + wm * 32 + mi * 16 + qr;
            const int c = colBlock + wn * 64 + ni * 8 + 2 * g;
            *(float2*)&Cp[(size_t)r * ldc + c]       = make_float2(acc[mi][ni][0], acc[mi][ni][1]);
            *(float2*)&Cp[(size_t)(r + 8) * ldc + c] = make_float2(acc[mi][ni][2], acc[mi][ni][3]);
        }
}

// ---------------------------------------------------------------------------
// Conversions f32 -> fp16
// ---------------------------------------------------------------------------
__global__ void __launch_bounds__(256)
convert_x_kernel(const float* __restrict__ x)
{
    const size_t i = ((size_t)blockIdx.x * 256 + threadIdx.x) * 8;
    float4 f0 = *(const float4*)(x + i);
    float4 f1 = *(const float4*)(x + i + 4);
    uint4 o;
    o.x = packh2(f0.x, f0.y); o.y = packh2(f0.z, f0.w);
    o.z = packh2(f1.x, f1.y); o.w = packh2(f1.z, f1.w);
    *(uint4*)(g_xh + i) = o;
}

__global__ void __launch_bounds__(256)
convert_w_kernel(const float* __restrict__ Bw,
                 const float* __restrict__ Cw,
                 const float* __restrict__ Dw)
{
    const int i = blockIdx.x * blockDim.x + threadIdx.x;
    if (i < SS * DD) g_Bw_h[i] = __float2half(Bw[i]);
    if (i < DD * SS) g_Cw_h[i] = __float2half(Cw[i]);
    if (i < DD * DD) g_Dw_h[i] = __float2half(Dw[i]);
}

// ---------------------------------------------------------------------------
// Sequential scan: one block per batch. 512 thr = (s in [0,128)) x (q quarters).
// ---------------------------------------------------------------------------
__global__ void __launch_bounds__(512)
scan_kernel(const float* __restrict__ A)
{
    __shared__ float st[SS];
    __shared__ float part[4][SS];

    const int tid = threadIdx.x;
    const int s = tid & 127;
    const int q = tid >> 7;

    float a[32];
    const float4* arp = (const float4*)(A + s * SS + q * 32);
#pragma unroll
    for (int j = 0; j < 8; ++j) {
        float4 v = arp[j];
        a[4 * j]     = v.x; a[4 * j + 1] = v.y;
        a[4 * j + 2] = v.z; a[4 * j + 3] = v.w;
    }

    if (tid < SS) st[tid] = 0.f;

    const int b = blockIdx.x;
    const float* bx = g_Bx + (size_t)b * TT * SS;
    __half* so = g_states_h + (size_t)b * TT * SS;

    float bxv = (q == 0) ? bx[s] : 0.f;
    __syncthreads();

    for (int t = 0; t < TT; ++t) {
        float p0 = 0.f, p1 = 0.f, p2 = 0.f, p3 = 0.f;
        const float4* stv = (const float4*)(st + q * 32);
#pragma unroll
        for (int j = 0; j < 8; ++j) {
            float4 v = stv[j];
            p0 = fmaf(a[4 * j],     v.x, p0);
            p1 = fmaf(a[4 * j + 1], v.y, p1);
            p2 = fmaf(a[4 * j + 2], v.z, p2);
            p3 = fmaf(a[4 * j + 3], v.w, p3);
        }
        part[q][s] = (p0 + p1) + (p2 + p3);
        __syncthreads();
        if (q == 0) {
            float v = part[0][s] + part[1][s] + part[2][s] + part[3][s] + bxv;
            v = fminf(fmaxf(v, -10.f), 10.f);
            st[s] = v;
            so[t * SS + s] = __float2half(v);
            if (t + 1 < TT) bxv = bx[(t + 1) * SS + s];
        }
        __syncthreads();
    }
}

// ---------------------------------------------------------------------------
// Fused gate + residual mix + LayerNorm. One block (128 threads) per row.
// ---------------------------------------------------------------------------
__global__ void __launch_bounds__(128)
mix_ln_kernel(const float* __restrict__ x,
              const float* __restrict__ gate_w,
              const float* __restrict__ gate_b,
              const float* __restrict__ gamma,
              const float* __restrict__ beta,
              float* __restrict__ io)
{
    __shared__ float red[4][2];

    const int row = blockIdx.x;
    const int tid = threadIdx.x;
    const int lane = tid & 31, w = tid >> 5;
    const float* xr = x + (size_t)row * DD;
    float* tr = io + (size_t)row * DD;

    float xs[6], ts[6];
    float l0 = 0.f, l1 = 0.f;
#pragma unroll
    for (int k = 0; k < 6; ++k) {
        const int i = tid + k * 128;
        xs[k] = xr[i];
        ts[k] = tr[i];
        l0 = fmaf(xs[k], gate_w[i], l0);
        l1 = fmaf(xs[k], gate_w[DD + i], l1);
    }
#pragma unroll
    for (int o = 16; o; o >>= 1) {
        l0 += __shfl_xor_sync(0xffffffffu, l0, o);
        l1 += __shfl_xor_sync(0xffffffffu, l1, o);
    }
    if (lane == 0) { red[w][0] = l0; red[w][1] = l1; }
    __syncthreads();
    l0 = red[0][0] + red[1][0] + red[2][0] + red[3][0] + gate_b[0];
    l1 = red[0][1] + red[1][1] + red[2][1] + red[3][1] + gate_b[1];

    const float mx = fmaxf(l0, l1);
    const float e0 = expf(l0 - mx), e1 = expf(l1 - mx);
    const float inv = 1.f / (e0 + e1);
    const float g0 = e0 * inv, g1 = e1 * inv;

    float mix[6];
    float s = 0.f, s2 = 0.f;
#pragma unroll
    for (int k = 0; k < 6; ++k) {
        mix[k] = g0 * ts[k] + g1 * xs[k];
        s += mix[k];
        s2 = fmaf(mix[k], mix[k], s2);
    }
    __syncthreads();
#pragma unroll
    for (int o = 16; o; o >>= 1) {
        s  += __shfl_xor_sync(0xffffffffu, s, o);
        s2 += __shfl_xor_sync(0xffffffffu, s2, o);
    }
    if (lane == 0) { red[w][0] = s; red[w][1] = s2; }
    __syncthreads();
    s  = red[0][0] + red[1][0] + red[2][0] + red[3][0];
    s2 = red[0][1] + red[1][1] + red[2][1] + red[3][1];

    const float mu = s * (1.f / DD);
    float var = s2 * (1.f / DD) - mu * mu;
    var = fmaxf(var, 0.f);
    const float rstd = rsqrtf(var + 1e-5f);

#pragma unroll
    for (int k = 0; k < 6; ++k) {
        const int i = tid + k * 128;
        tr[i] = (mix[k] - mu) * rstd * gamma[i] + beta[i];
    }
}

// ---------------------------------------------------------------------------
// Launch
// ---------------------------------------------------------------------------
extern "C" void kernel_launch(void* const* d_in, const int* in_sizes, int n_in,
                              void* d_out, int out_size)
{
    const float* x      = (const float*)d_in[0];
    const float* A      = (const float*)d_in[1];
    const float* B_w    = (const float*)d_in[2];
    const float* C_w    = (const float*)d_in[3];
    const float* D_w    = (const float*)d_in[4];
    const float* gate_w = (const float*)d_in[5];
    const float* gate_b = (const float*)d_in[6];
    const float* gamma  = (const float*)d_in[7];
    const float* beta   = (const float*)d_in[8];
    float* out = (float*)d_out;

    float  *Bx = nullptr;
    __half *Sh = nullptr, *Xh = nullptr, *BwH = nullptr, *CwH = nullptr, *DwH = nullptr;
    cudaGetSymbolAddress((void**)&Bx,  g_Bx);
    cudaGetSymbolAddress((void**)&Sh,  g_states_h);
    cudaGetSymbolAddress((void**)&Xh,  g_xh);
    cudaGetSymbolAddress((void**)&BwH, g_Bw_h);
    cudaGetSymbolAddress((void**)&CwH, g_Cw_h);
    cudaGetSymbolAddress((void**)&DwH, g_Dw_h);

    // 0) conversions f32 -> fp16
    convert_x_kernel<<<(NROWS * DD) / (256 * 8), 256>>>(x);
    convert_w_kernel<<<(DD * DD + 255) / 256, 256>>>(B_w, C_w, D_w);

    // 1) Bx = x_h @ B_w^T   [32768 x 128], K=768; BM=64 tiles for wave balance
    gemm_ca<64><<<dim3(1, NROWS / 64), 128>>>(
        Xh, BwH, DD, Xh, BwH, 0, Bx, SS);

    // 2) sequential scan -> states (fp16)
    scan_kernel<<<BB, 512>>>(A);

    // 3) out = states_h @ C_w^T + x_h @ D_w^T   [32768 x 768], K = 128 + 768
    gemm_ca<128><<<dim3(DD / 128, NROWS / 128), 256>>>(
        Sh, CwH, SS, Xh, DwH, DD, out, DD);

    // 4) gate + residual mix + LayerNorm (in place on d_out)
    mix_ln_kernel<<<NROWS, 128>>>(x, gate_w, gate_b, gamma, beta, out);
}